// round 10
// baseline (speedup 1.0000x reference)
#include <cuda_runtime.h>
#include <cuda_bf16.h>
#include <cstdint>
#include <math.h>

#define N_OSC 32
#define CONVC 1000.0f
#define NBLK 148
#define TPB  1024   // 32 warps

// -------- scratch (no allocations allowed) --------
__device__ __align__(16) float g_h1[4096];
__device__ __align__(16) float g_h2[4096];
__device__ __align__(16) float g_params[2112];
__device__ __align__(16) float g_cpg[64];
__device__ __align__(16) float g_h3[2048];
__device__ unsigned g_count[8];   // zero-init; each barrier resets itself
__device__ unsigned g_flag[8];    // monotonically increasing epochs

// -------- cp.async helpers --------
__device__ __forceinline__ void cp_async16(unsigned dst, const void* src) {
    asm volatile("cp.async.cg.shared.global [%0], [%1], 16;" :: "r"(dst), "l"(src));
}
__device__ __forceinline__ void cp_async4(unsigned dst, const void* src) {
    asm volatile("cp.async.ca.shared.global [%0], [%1], 4;" :: "r"(dst), "l"(src));
}
__device__ __forceinline__ void cp_commit() {
    asm volatile("cp.async.commit_group;");
}
template <int N>
__device__ __forceinline__ void cp_wait() {
    asm volatile("cp.async.wait_group %0;" :: "n"(N));
}

// -------- grid-wide barrier (all NBLK blocks co-resident) --------
__device__ __forceinline__ void grid_barrier(int id, unsigned base) {
    __syncthreads();
    if (threadIdx.x == 0) {
        __threadfence();
        if (atomicAdd(&g_count[id], 1u) == NBLK - 1) {
            g_count[id] = 0;
            __threadfence();
            atomicAdd(&g_flag[id], 1u);
        } else {
            volatile unsigned* f = &g_flag[id];
            while (*f == base) { }
        }
        __threadfence();
    }
    __syncthreads();
}

__device__ __forceinline__ float warp_sum(float s) {
    #pragma unroll
    for (int o = 16; o; o >>= 1) s += __shfl_xor_sync(0xFFFFFFFFu, s, o);
    return s;
}

// ===== warp-per-row matvec via cp.async double-buffered pipeline =====
// Row length C floats (C % 512 == 0, W 16B-aligned rows). Chunk = 512 floats
// (2 KB); per-warp smem slice = 4 KB (2 chunks). r = b + NBLK*w striping.
template <bool RELU, int ROWS, int C>
__device__ __forceinline__ void layer_cp16(const float* __restrict__ W,
                                           const float* __restrict__ bias,
                                           const float* __restrict__ x,
                                           float* __restrict__ y,
                                           int b, int w, int lane,
                                           unsigned char* sh_raw, unsigned sh_u32) {
    int r = b + NBLK * w;
    if (r >= ROWS) return;
    constexpr int NCH = C / 512;
    const float* __restrict__ wrow = W + (size_t)r * C;
    const float4* __restrict__ x4 = reinterpret_cast<const float4*>(x);
    unsigned sb = sh_u32 + w * 4096;

    // prologue: chunks 0,1
    #pragma unroll
    for (int p = 0; p < 2; ++p) {
        if (p < NCH) {
            unsigned dst = sb + p * 2048 + lane * 16;
            const float* src = wrow + p * 512 + lane * 4;
            #pragma unroll
            for (int i = 0; i < 4; ++i) cp_async16(dst + i * 512, src + i * 128);
        }
        cp_commit();
    }

    const float4* sl4 = reinterpret_cast<const float4*>(sh_raw + w * 4096);
    float s = 0.f, s2 = 0.f;
    #pragma unroll
    for (int c = 0; c < NCH; ++c) {
        cp_wait<1>();
        __syncwarp();
        const float4* buf = sl4 + (c & 1) * 128;
        #pragma unroll
        for (int i = 0; i < 4; ++i) {
            float4 a = buf[lane + i * 32];
            float4 v = x4[c * 128 + lane + i * 32];
            s  += a.x * v.x + a.y * v.y;
            s2 += a.z * v.z + a.w * v.w;
        }
        __syncwarp();
        int pc = c + 2;
        if (pc < NCH) {
            unsigned dst = sb + (pc & 1) * 2048 + lane * 16;
            const float* src = wrow + pc * 512 + lane * 4;
            #pragma unroll
            for (int i = 0; i < 4; ++i) cp_async16(dst + i * 512, src + i * 128);
        }
        cp_commit();
    }
    s = warp_sum(s + s2);
    if (lane == 0) {
        s += bias[r];
        if (RELU) s = fmaxf(s, 0.f);
        y[r] = s;
    }
}

// ============ THE WHOLE NETWORK, one persistent kernel ============
__global__ __launch_bounds__(TPB, 1) void cpg_net_kernel(
        const float* __restrict__ state, const float* __restrict__ x,
        const float* __restrict__ ts,
        const float* __restrict__ iW0, const float* __restrict__ ib0,
        const float* __restrict__ iW1, const float* __restrict__ ib1,
        const float* __restrict__ iW2, const float* __restrict__ ib2,
        const float* __restrict__ oW0, const float* __restrict__ ob0,
        const float* __restrict__ oW1, const float* __restrict__ ob1,
        const float* __restrict__ oW2, const float* __restrict__ ob2,
        float* __restrict__ out /* [new_state(96), out(1024)] */) {
    extern __shared__ __align__(16) unsigned char sh_raw[];  // 32 warps * 4KB
    __shared__ unsigned s_base[8];
    __shared__ float s_cw[N_OSC * 33];
    __shared__ float s_pb[N_OSC * 33];
    __shared__ float s_ph[N_OSC];

    unsigned sh_u32 = (unsigned)__cvta_generic_to_shared(sh_raw);
    float* shf = reinterpret_cast<float*>(sh_raw);

    int b    = blockIdx.x;
    int w    = threadIdx.x >> 5;
    int lane = threadIdx.x & 31;

    if (threadIdx.x < 8) s_base[threadIdx.x] = g_flag[threadIdx.x];
    __syncthreads();

    // ---- L1: h1 = relu(iW0 @ [x, ts] + ib0)  [4096 x 2049] ----
    // 4B cp.async (rows only 4B-aligned). 4 chunks of 512 + scalar tail.
    {
        int r = b + NBLK * w;
        if (r < 4096) {
            const float* __restrict__ wrow = iW0 + (size_t)r * 2049;
            unsigned sb = sh_u32 + w * 4096;
            #pragma unroll
            for (int p = 0; p < 2; ++p) {
                unsigned dst = sb + p * 2048 + lane * 4;
                const float* src = wrow + p * 512 + lane;
                #pragma unroll
                for (int j = 0; j < 16; ++j) cp_async4(dst + j * 128, src + j * 32);
                cp_commit();
            }
            float s = 0.f;
            float* slice = shf + w * 1024;
            #pragma unroll
            for (int c = 0; c < 4; ++c) {
                cp_wait<1>();
                __syncwarp();
                const float* buf = slice + (c & 1) * 512;
                #pragma unroll
                for (int j = 0; j < 16; ++j) {
                    int idx = lane + j * 32;
                    s += buf[idx] * __ldg(&x[c * 512 + idx]);
                }
                __syncwarp();
                int pc = c + 2;
                if (pc < 4) {
                    unsigned dst = sb + (pc & 1) * 2048 + lane * 4;
                    const float* src = wrow + pc * 512 + lane;
                    #pragma unroll
                    for (int j = 0; j < 16; ++j) cp_async4(dst + j * 128, src + j * 32);
                }
                cp_commit();
            }
            s = warp_sum(s);
            if (lane == 0) {
                s += wrow[2048] * ts[0] + ib0[r];
                g_h1[r] = fmaxf(s, 0.f);
            }
        }
    }
    grid_barrier(0, s_base[0]);

    // ---- L2: h2 = relu(iW1 @ h1 + ib1)   [4096 x 4096] ----
    layer_cp16<true, 4096, 4096>(iW1, ib1, g_h1, g_h2, b, w, lane, sh_raw, sh_u32);
    grid_barrier(1, s_base[1]);

    // ---- L3: params = iW2 @ h2 + ib2     [2112 x 4096] ----
    layer_cp16<false, 2112, 4096>(iW2, ib2, g_h2, g_params, b, w, lane, sh_raw, sh_u32);
    grid_barrier(2, s_base[2]);

    // ---- ODE: RK4 3/8, single warp on block 0 ----
    // Replicates reference slicing exactly: phase_dots go into the a_dot
    // slot; post-step "ph" is read from that slot for cpg_out.
    if (b == 0 && threadIdx.x < 32) {
        int i = lane;
        for (int idx = lane; idx < N_OSC * N_OSC; idx += 32) {
            int ii = idx >> 5, jj = idx & 31;
            s_cw[ii * 33 + jj] = g_params[2 * N_OSC + idx];
            s_pb[ii * 33 + jj] = g_params[2 * N_OSC + N_OSC * N_OSC + idx];
        }
        __syncwarp();

        float h   = ts[0];
        float ya  = state[i];
        float yad = state[N_OSC + i];
        float yph = state[2 * N_OSC + i];
        float ia  = g_params[i];
        float ifr = g_params[N_OSC + i];

        float k1a, k1ad, k1ph, k2a, k2ad, k2ph, k3a, k3ad, k3ph, k4a, k4ad, k4ph;

        auto stage = [&](float ea, float ead, float eph,
                         float& ka, float& kad, float& kph) {
            s_ph[i] = eph;
            __syncwarp();
            float t = 0.f;
            #pragma unroll
            for (int j = 0; j < N_OSC; ++j)
                t += s_cw[i * 33 + j] * __sinf(s_ph[j] - eph - s_pb[i * 33 + j]);
            __syncwarp();
            kad = ifr + ea * t;                                // phase_dots
            ka  = ead;                                         // a_dot
            kph = CONVC * (CONVC * 0.25f * (ia - ea) - ead);   // a_dd
        };

        stage(ya, yad, yph, k1a, k1ad, k1ph);
        stage(ya + h * k1a / 3.0f, yad + h * k1ad / 3.0f, yph + h * k1ph / 3.0f,
              k2a, k2ad, k2ph);
        stage(ya + h * (k2a - k1a / 3.0f),
              yad + h * (k2ad - k1ad / 3.0f),
              yph + h * (k2ph - k1ph / 3.0f),
              k3a, k3ad, k3ph);
        stage(ya + h * (k1a - k2a + k3a),
              yad + h * (k1ad - k2ad + k3ad),
              yph + h * (k1ph - k2ph + k3ph),
              k4a, k4ad, k4ph);

        float yna  = ya  + h * 0.125f * (k1a  + 3.0f * (k2a  + k3a)  + k4a);
        float ynad = yad + h * 0.125f * (k1ad + 3.0f * (k2ad + k3ad) + k4ad);
        float ynph = yph + h * 0.125f * (k1ph + 3.0f * (k2ph + k3ph) + k4ph);

        out[i]             = yna;
        out[N_OSC + i]     = ynad;
        out[2 * N_OSC + i] = ynph;

        // reference reads ns[:n] as a and ns[n:2n] (the a_dot slot) as ph
        g_cpg[i]         = yna * __cosf(ynad);
        g_cpg[N_OSC + i] = yna * __sinf(ynad);
    }
    grid_barrier(3, s_base[3]);

    // ---- L4: h3 = relu(oW0 @ cpg + ob0)  [2048 x 64] ----
    {
        int r = b + NBLK * w;
        if (r < 2048) {
            float2 ww = reinterpret_cast<const float2*>(oW0 + (size_t)r * 64)[lane];
            float2 cc = reinterpret_cast<const float2*>(g_cpg)[lane];
            float s = warp_sum(ww.x * cc.x + ww.y * cc.y);
            if (lane == 0) g_h3[r] = fmaxf(s + ob0[r], 0.f);
        }
    }
    grid_barrier(4, s_base[4]);

    // ---- L5: h4 = relu(oW1 @ h3 + ob1)   [2048 x 2048] ----
    layer_cp16<true, 2048, 2048>(oW1, ob1, g_h3, g_h1 /*reuse as h4*/, b, w, lane, sh_raw, sh_u32);
    grid_barrier(5, s_base[5]);

    // ---- L6: out = oW2 @ h4 + ob2        [1024 x 2048] -> out[96:1120] ----
    layer_cp16<false, 1024, 2048>(oW2, ob2, g_h1, out + 96, b, w, lane, sh_raw, sh_u32);
}

extern "C" void kernel_launch(void* const* d_in, const int* in_sizes, int n_in,
                              void* d_out, int out_size) {
    const float* state = (const float*)d_in[0];
    const float* x     = (const float*)d_in[1];
    const float* ts    = (const float*)d_in[2];
    const float* iW0   = (const float*)d_in[3];
    const float* ib0   = (const float*)d_in[4];
    const float* iW1   = (const float*)d_in[5];
    const float* ib1   = (const float*)d_in[6];
    const float* iW2   = (const float*)d_in[7];
    const float* ib2   = (const float*)d_in[8];
    const float* oW0   = (const float*)d_in[9];
    const float* ob0   = (const float*)d_in[10];
    const float* oW1   = (const float*)d_in[11];
    const float* ob1   = (const float*)d_in[12];
    const float* oW2   = (const float*)d_in[13];
    const float* ob2   = (const float*)d_in[14];
    float* out = (float*)d_out;   // [new_state(96), out(1024)]

    const int SMEM = 32 * 4096;   // 128 KB dynamic
    cudaFuncSetAttribute(cpg_net_kernel,
                         cudaFuncAttributeMaxDynamicSharedMemorySize, SMEM);

    cpg_net_kernel<<<NBLK, TPB, SMEM>>>(state, x, ts,
                                        iW0, ib0, iW1, ib1, iW2, ib2,
                                        oW0, ob0, oW1, ob1, oW2, ob2, out);
}

// round 11
// speedup vs baseline: 1.0936x; 1.0936x over previous
#include <cuda_runtime.h>
#include <cuda_bf16.h>
#include <cstdint>
#include <math.h>

#define N_OSC 32
#define CONVC 1000.0f
#define NBLK 148
#define TPB  1024            // 4 groups x 256 threads
#define NGRP 592             // 148 * 4

// -------- scratch (no allocations allowed) --------
__device__ __align__(16) float g_h1[4096];   // h1, later reused as h4
__device__ __align__(16) float g_h2[4096];
__device__ __align__(16) float g_params[2112];
__device__ __align__(16) float g_h3[2048];
__device__ unsigned g_count[8];   // zero-init; each barrier resets itself
__device__ unsigned g_flag[8];    // monotonically increasing epochs

// -------- grid-wide barrier (all NBLK blocks co-resident) --------
__device__ __forceinline__ void grid_barrier(int id, unsigned base) {
    __syncthreads();
    if (threadIdx.x == 0) {
        __threadfence();
        if (atomicAdd(&g_count[id], 1u) == NBLK - 1) {
            g_count[id] = 0;
            __threadfence();
            atomicAdd(&g_flag[id], 1u);
        } else {
            volatile unsigned* f = &g_flag[id];
            while (*f == base) { }
        }
        __threadfence();
    }
    __syncthreads();
}

__device__ __forceinline__ float warp_sum(float s) {
    #pragma unroll
    for (int o = 16; o; o >>= 1) s += __shfl_xor_sync(0xFFFFFFFFu, s, o);
    return s;
}

// named barrier for one 256-thread group (ids 1..4; 0 is __syncthreads)
__device__ __forceinline__ void bar_g(int id) {
    asm volatile("bar.sync %0, 256;" :: "r"(id) : "memory");
}

// ===== group-per-row matvec (256 thr/row) with next-row prefetch =====
// C = N4*1024 cols. Thread t holds N4 float4 of the row; weights __ldcs
// (single-use, evict-first). Next row's weights load before the reduction.
template <bool RELU, int ROWS, int N4>
__device__ __forceinline__ void layer_grp(const float* __restrict__ W,
                                          const float* __restrict__ bias,
                                          const float* __restrict__ x,
                                          float* __restrict__ y,
                                          int g, int lg, int t, int lane, int wig,
                                          float* s_red /* [4][2][8] */) {
    constexpr int C = N4 * 1024;
    const float4* __restrict__ x4 = reinterpret_cast<const float4*>(x);

    int r = g;
    float4 w0[N4];
    if (r < ROWS) {
        const float4* wr = reinterpret_cast<const float4*>(W + (size_t)r * C);
        #pragma unroll
        for (int k = 0; k < N4; ++k) w0[k] = __ldcs(&wr[t + k * 256]);
    }
    int p = 0;
    while (r < ROWS) {
        int rn = r + NGRP;
        float4 w1[N4];
        if (rn < ROWS) {
            const float4* wr = reinterpret_cast<const float4*>(W + (size_t)rn * C);
            #pragma unroll
            for (int k = 0; k < N4; ++k) w1[k] = __ldcs(&wr[t + k * 256]);
        }
        float s = 0.f, s2 = 0.f;
        #pragma unroll
        for (int k = 0; k < N4; ++k) {
            float4 v = __ldg(&x4[t + k * 256]);
            s  += w0[k].x * v.x + w0[k].y * v.y;
            s2 += w0[k].z * v.z + w0[k].w * v.w;
        }
        s = warp_sum(s + s2);
        if (lane == 0) s_red[(lg * 2 + p) * 8 + wig] = s;
        bar_g(lg + 1);
        if (t == 0) {
            const float* rr = &s_red[(lg * 2 + p) * 8];
            float v = rr[0] + rr[1] + rr[2] + rr[3] + rr[4] + rr[5] + rr[6] + rr[7]
                    + bias[r];
            if (RELU) v = fmaxf(v, 0.f);
            y[r] = v;
        }
        #pragma unroll
        for (int k = 0; k < N4; ++k) w0[k] = w1[k];
        r = rn; p ^= 1;
    }
}

// ============ THE WHOLE NETWORK, one persistent kernel ============
__global__ __launch_bounds__(TPB, 1) void cpg_net_kernel(
        const float* __restrict__ state, const float* __restrict__ x,
        const float* __restrict__ ts,
        const float* __restrict__ iW0, const float* __restrict__ ib0,
        const float* __restrict__ iW1, const float* __restrict__ ib1,
        const float* __restrict__ iW2, const float* __restrict__ ib2,
        const float* __restrict__ oW0, const float* __restrict__ ob0,
        const float* __restrict__ oW1, const float* __restrict__ ob1,
        const float* __restrict__ oW2, const float* __restrict__ ob2,
        float* __restrict__ out /* [new_state(96), out(1024)] */) {
    __shared__ float s_red[4 * 2 * 8];
    __shared__ unsigned s_base[8];
    __shared__ float s_cw[N_OSC * 33];
    __shared__ float s_pb[N_OSC * 33];
    __shared__ float s_ph[N_OSC];
    __shared__ float s_cpg[2 * N_OSC];

    int b    = blockIdx.x;
    int tid  = threadIdx.x;
    int lg   = tid >> 8;          // local group 0..3
    int t    = tid & 255;         // thread in group
    int lane = t & 31;
    int wig  = t >> 5;            // warp in group 0..7
    int g    = (b << 2) | lg;     // global group 0..591

    if (tid < 8) s_base[tid] = g_flag[tid];
    __syncthreads();

    // ---- L1: h1 = relu(iW0 @ [x, ts] + ib0)  [4096 x 2049], scalar ----
    {
        float tsv = __ldg(ts);
        int r = g;
        float w0[8], w0t = 0.f;
        if (r < 4096) {
            const float* wr = iW0 + (size_t)r * 2049;
            #pragma unroll
            for (int k = 0; k < 8; ++k) w0[k] = __ldcs(wr + t + k * 256);
            if (t == 0) w0t = __ldcs(wr + 2048);
        }
        int p = 0;
        while (r < 4096) {
            int rn = r + NGRP;
            float w1[8], w1t = 0.f;
            if (rn < 4096) {
                const float* wr = iW0 + (size_t)rn * 2049;
                #pragma unroll
                for (int k = 0; k < 8; ++k) w1[k] = __ldcs(wr + t + k * 256);
                if (t == 0) w1t = __ldcs(wr + 2048);
            }
            float s = 0.f;
            #pragma unroll
            for (int k = 0; k < 8; ++k) s += w0[k] * __ldg(x + t + k * 256);
            s = warp_sum(s);
            if (lane == 0) s_red[(lg * 2 + p) * 8 + wig] = s;
            bar_g(lg + 1);
            if (t == 0) {
                const float* rr = &s_red[(lg * 2 + p) * 8];
                float v = rr[0] + rr[1] + rr[2] + rr[3] + rr[4] + rr[5] + rr[6] + rr[7]
                        + w0t * tsv + ib0[r];
                g_h1[r] = fmaxf(v, 0.f);
            }
            #pragma unroll
            for (int k = 0; k < 8; ++k) w0[k] = w1[k];
            w0t = w1t;
            r = rn; p ^= 1;
        }
    }
    grid_barrier(0, s_base[0]);

    // ---- L2: h2 = relu(iW1 @ h1 + ib1)   [4096 x 4096] ----
    layer_grp<true, 4096, 4>(iW1, ib1, g_h1, g_h2, g, lg, t, lane, wig, s_red);
    grid_barrier(1, s_base[1]);

    // ---- L3: params = iW2 @ h2 + ib2     [2112 x 4096] ----
    layer_grp<false, 2112, 4>(iW2, ib2, g_h2, g_params, g, lg, t, lane, wig, s_red);
    grid_barrier(2, s_base[2]);

    // ---- ODE: RK4 3/8, warp 0 of EVERY block (redundant; removes 2 grid
    // barriers). Replicates reference slicing exactly: phase_dots go into
    // the a_dot slot; post-step "ph" is read from that slot for cpg_out.
    if (tid < 32) {
        int i = lane;
        for (int idx = lane; idx < N_OSC * N_OSC; idx += 32) {
            int ii = idx >> 5, jj = idx & 31;
            s_cw[ii * 33 + jj] = g_params[2 * N_OSC + idx];
            s_pb[ii * 33 + jj] = g_params[2 * N_OSC + N_OSC * N_OSC + idx];
        }
        __syncwarp();

        float h   = __ldg(ts);
        float ya  = __ldg(state + i);
        float yad = __ldg(state + N_OSC + i);
        float yph = __ldg(state + 2 * N_OSC + i);
        float ia  = g_params[i];
        float ifr = g_params[N_OSC + i];

        float k1a, k1ad, k1ph, k2a, k2ad, k2ph, k3a, k3ad, k3ph, k4a, k4ad, k4ph;

        auto stage = [&](float ea, float ead, float eph,
                         float& ka, float& kad, float& kph) {
            s_ph[i] = eph;
            __syncwarp();
            float tt = 0.f;
            #pragma unroll
            for (int j = 0; j < N_OSC; ++j)
                tt += s_cw[i * 33 + j] * __sinf(s_ph[j] - eph - s_pb[i * 33 + j]);
            __syncwarp();
            kad = ifr + ea * tt;                               // phase_dots
            ka  = ead;                                         // a_dot
            kph = CONVC * (CONVC * 0.25f * (ia - ea) - ead);   // a_dd
        };

        stage(ya, yad, yph, k1a, k1ad, k1ph);
        stage(ya + h * k1a / 3.0f, yad + h * k1ad / 3.0f, yph + h * k1ph / 3.0f,
              k2a, k2ad, k2ph);
        stage(ya + h * (k2a - k1a / 3.0f),
              yad + h * (k2ad - k1ad / 3.0f),
              yph + h * (k2ph - k1ph / 3.0f),
              k3a, k3ad, k3ph);
        stage(ya + h * (k1a - k2a + k3a),
              yad + h * (k1ad - k2ad + k3ad),
              yph + h * (k1ph - k2ph + k3ph),
              k4a, k4ad, k4ph);

        float yna  = ya  + h * 0.125f * (k1a  + 3.0f * (k2a  + k3a)  + k4a);
        float ynad = yad + h * 0.125f * (k1ad + 3.0f * (k2ad + k3ad) + k4ad);
        float ynph = yph + h * 0.125f * (k1ph + 3.0f * (k2ph + k3ph) + k4ph);

        if (b == 0) {
            out[i]             = yna;
            out[N_OSC + i]     = ynad;
            out[2 * N_OSC + i] = ynph;
        }
        // reference reads ns[:n] as a and ns[n:2n] (the a_dot slot) as ph
        s_cpg[i]         = yna * __cosf(ynad);
        s_cpg[N_OSC + i] = yna * __sinf(ynad);
    }
    __syncthreads();   // s_cpg ready block-locally (no grid barrier needed)

    // ---- L4: h3 = relu(oW0 @ cpg + ob0)  [2048 x 64], warp-per-row ----
    {
        int r = (tid >> 5) * NBLK + b;    // one row per warp, unique
        if (r < 2048) {
            float2 ww = __ldcs(reinterpret_cast<const float2*>(oW0 + (size_t)r * 64) + lane);
            float2 cc = reinterpret_cast<const float2*>(s_cpg)[lane];
            float s = warp_sum(ww.x * cc.x + ww.y * cc.y);
            if (lane == 0) g_h3[r] = fmaxf(s + ob0[r], 0.f);
        }
    }
    grid_barrier(3, s_base[3]);

    // ---- L5: h4 = relu(oW1 @ h3 + ob1)   [2048 x 2048] ----
    layer_grp<true, 2048, 2>(oW1, ob1, g_h3, g_h1 /*reuse as h4*/, g, lg, t, lane, wig, s_red);
    grid_barrier(4, s_base[4]);

    // ---- L6: out = oW2 @ h4 + ob2        [1024 x 2048] -> out[96:1120] ----
    layer_grp<false, 1024, 2>(oW2, ob2, g_h1, out + 96, g, lg, t, lane, wig, s_red);
}

extern "C" void kernel_launch(void* const* d_in, const int* in_sizes, int n_in,
                              void* d_out, int out_size) {
    const float* state = (const float*)d_in[0];
    const float* x     = (const float*)d_in[1];
    const float* ts    = (const float*)d_in[2];
    const float* iW0   = (const float*)d_in[3];
    const float* ib0   = (const float*)d_in[4];
    const float* iW1   = (const float*)d_in[5];
    const float* ib1   = (const float*)d_in[6];
    const float* iW2   = (const float*)d_in[7];
    const float* ib2   = (const float*)d_in[8];
    const float* oW0   = (const float*)d_in[9];
    const float* ob0   = (const float*)d_in[10];
    const float* oW1   = (const float*)d_in[11];
    const float* ob1   = (const float*)d_in[12];
    const float* oW2   = (const float*)d_in[13];
    const float* ob2   = (const float*)d_in[14];
    float* out = (float*)d_out;   // [new_state(96), out(1024)]

    cpg_net_kernel<<<NBLK, TPB>>>(state, x, ts,
                                  iW0, ib0, iW1, ib1, iW2, ib2,
                                  oW0, ob0, oW1, ob1, oW2, ob2, out);
}

// round 12
// speedup vs baseline: 1.6059x; 1.4684x over previous
#include <cuda_runtime.h>
#include <cuda_bf16.h>
#include <cstdint>
#include <math.h>

#define N_OSC 32
#define CONVC 1000.0f

// -------- scratch (no allocations allowed) --------
__device__ __align__(16) float g_h1[4096];
__device__ __align__(16) float g_h2[4096];
__device__ __align__(16) float g_params[2112];
__device__ __align__(16) float g_cpg[64];
__device__ __align__(16) float g_h3[2048];
__device__ __align__(16) float g_h4[2048];

// ============ block-per-row matvec with PDL weight prefetch ============
// STREAM=true -> weights loaded with __ldcs (evict-first): keeps the big
// single-use matrix from evicting the L2-resident weight set between
// graph replays. STREAM=false -> default .ca load (persist in L2).
template <bool RELU, int C4, bool STREAM>
__global__ __launch_bounds__(256) void matvec_b(const float* __restrict__ W,
                                                const float* __restrict__ b,
                                                const float* __restrict__ x,
                                                float* __restrict__ y) {
    int row = blockIdx.x;
    const float4* __restrict__ w4 = reinterpret_cast<const float4*>(W) + (size_t)row * C4;
    const float4* __restrict__ x4 = reinterpret_cast<const float4*>(x);

    float4 wreg[C4 / 256];
    #pragma unroll
    for (int k = 0; k < C4 / 256; ++k)
        wreg[k] = STREAM ? __ldcs(&w4[threadIdx.x + k * 256])
                         : w4[threadIdx.x + k * 256];
    float bias = (threadIdx.x == 0) ? b[row] : 0.f;

    cudaGridDependencySynchronize();   // wait for predecessor's x

    float s = 0.f;
    #pragma unroll
    for (int k = 0; k < C4 / 256; ++k) {
        float4 v = x4[threadIdx.x + k * 256];
        s += wreg[k].x * v.x + wreg[k].y * v.y + wreg[k].z * v.z + wreg[k].w * v.w;
    }

    #pragma unroll
    for (int o = 16; o; o >>= 1) s += __shfl_xor_sync(0xFFFFFFFFu, s, o);
    __shared__ float red[8];
    if ((threadIdx.x & 31) == 0) red[threadIdx.x >> 5] = s;
    __syncthreads();
    if (threadIdx.x < 8) {
        float v = red[threadIdx.x];
        #pragma unroll
        for (int o = 4; o; o >>= 1) v += __shfl_xor_sync(0xFFu, v, o);
        if (threadIdx.x == 0) {
            v += bias;
            if (RELU) v = fmaxf(v, 0.f);
            y[row] = v;
        }
    }
}

// ============ layer 1: cols = 2049 (2048 from x + timestep) ============
// iW0 kept L2-resident (default loads).
__global__ __launch_bounds__(256) void matvec_l1(const float* __restrict__ W,
                                                 const float* __restrict__ b,
                                                 const float* __restrict__ x,
                                                 const float* __restrict__ ts,
                                                 float* __restrict__ y) {
    int row = blockIdx.x;
    const float* __restrict__ w = W + (size_t)row * 2049;

    float s = 0.f;
    #pragma unroll
    for (int k = 0; k < 8; ++k) {
        int c = threadIdx.x + k * 256;
        s += w[c] * x[c];
    }
    if (threadIdx.x == 0) s += w[2048] * ts[0];

    #pragma unroll
    for (int o = 16; o; o >>= 1) s += __shfl_xor_sync(0xFFFFFFFFu, s, o);
    __shared__ float red[8];
    if ((threadIdx.x & 31) == 0) red[threadIdx.x >> 5] = s;
    __syncthreads();
    if (threadIdx.x < 8) {
        float v = red[threadIdx.x];
        #pragma unroll
        for (int o = 4; o; o >>= 1) v += __shfl_xor_sync(0xFFu, v, o);
        if (threadIdx.x == 0) {
            v += b[row];
            y[row] = fmaxf(v, 0.f);
        }
    }
}

// ============ small layer [2048 x 64]: warp-per-row, PDL prefetch ============
__global__ void matvec_small64(const float* __restrict__ W,
                               const float* __restrict__ b,
                               const float* __restrict__ x,
                               float* __restrict__ y, int rows) {
    int warp = (blockIdx.x * blockDim.x + threadIdx.x) >> 5;
    int lane = threadIdx.x & 31;

    float4 w = make_float4(0.f, 0.f, 0.f, 0.f);
    float bias = 0.f;
    if (warp < rows) {
        if (lane < 16)
            w = reinterpret_cast<const float4*>(W + (size_t)warp * 64)[lane];
        if (lane == 0) bias = b[warp];
    }

    cudaGridDependencySynchronize();   // wait for cpg

    if (warp >= rows) return;
    float s = 0.f;
    if (lane < 16) {
        float4 v = reinterpret_cast<const float4*>(x)[lane];
        s = w.x * v.x + w.y * v.y + w.z * v.z + w.w * v.w;
    }
    #pragma unroll
    for (int o = 8; o; o >>= 1) s += __shfl_xor_sync(0xFFFFFFFFu, s, o);
    if (lane == 0) y[warp] = fmaxf(s + bias, 0.f);
}

// ============ CPG ODE, RK4 3/8 rule — single warp, registers + __sinf ============
// Lane i <-> oscillator i. Coupling row cw[i][:], pb[i][:] in registers.
// Only phases cross lanes, via s_ph[] (same-address LDS = broadcast).
// Replicates reference slicing exactly: phase_dots go into the a_dot slot,
// and post-step "ph" is read from that slot for cpg_out.
__global__ __launch_bounds__(32) void cpg_ode_kernel(
        const float* __restrict__ state,
        const float* __restrict__ ts,
        float* __restrict__ d_out_state /* 96 floats */) {
    __shared__ float s_ph[N_OSC];

    int i = threadIdx.x;   // lane = oscillator

    // independent inputs: prefetch before dependency sync
    float h   = ts[0];
    float ya  = state[i];
    float yad = state[N_OSC + i];
    float yph = state[2 * N_OSC + i];

    cudaGridDependencySynchronize();   // wait for g_params (layer-3 output)

    float cw[N_OSC], pb[N_OSC];
    {
        const float4* cw4 = reinterpret_cast<const float4*>(g_params + 2 * N_OSC) + i * 8;
        const float4* pb4 = reinterpret_cast<const float4*>(g_params + 2 * N_OSC + N_OSC * N_OSC) + i * 8;
        #pragma unroll
        for (int k = 0; k < 8; ++k) {
            float4 c = cw4[k];
            cw[4 * k + 0] = c.x; cw[4 * k + 1] = c.y; cw[4 * k + 2] = c.z; cw[4 * k + 3] = c.w;
            float4 p = pb4[k];
            pb[4 * k + 0] = p.x; pb[4 * k + 1] = p.y; pb[4 * k + 2] = p.z; pb[4 * k + 3] = p.w;
        }
    }
    float ia  = g_params[i];
    float ifr = g_params[N_OSC + i];

    float k1a, k1ad, k1ph, k2a, k2ad, k2ph, k3a, k3ad, k3ph, k4a, k4ad, k4ph;

    auto stage = [&](float ea, float ead, float eph,
                     float& ka, float& kad, float& kph) {
        s_ph[i] = eph;
        __syncwarp();
        float t = 0.f;
        #pragma unroll
        for (int j = 0; j < N_OSC; ++j)
            t += cw[j] * __sinf(s_ph[j] - eph - pb[j]);
        __syncwarp();
        kad = ifr + ea * t;                                // phase_dots
        ka  = ead;                                         // a_dot
        kph = CONVC * (CONVC * 0.25f * (ia - ea) - ead);   // a_dd
    };

    stage(ya, yad, yph, k1a, k1ad, k1ph);
    stage(ya + h * k1a / 3.0f, yad + h * k1ad / 3.0f, yph + h * k1ph / 3.0f,
          k2a, k2ad, k2ph);
    stage(ya + h * (k2a - k1a / 3.0f),
          yad + h * (k2ad - k1ad / 3.0f),
          yph + h * (k2ph - k1ph / 3.0f),
          k3a, k3ad, k3ph);
    stage(ya + h * (k1a - k2a + k3a),
          yad + h * (k1ad - k2ad + k3ad),
          yph + h * (k1ph - k2ph + k3ph),
          k4a, k4ad, k4ph);

    float yna  = ya  + h * 0.125f * (k1a  + 3.0f * (k2a  + k3a)  + k4a);
    float ynad = yad + h * 0.125f * (k1ad + 3.0f * (k2ad + k3ad) + k4ad);
    float ynph = yph + h * 0.125f * (k1ph + 3.0f * (k2ph + k3ph) + k4ph);

    d_out_state[i]             = yna;
    d_out_state[N_OSC + i]     = ynad;
    d_out_state[2 * N_OSC + i] = ynph;

    // reference reads ns[:n] as a and ns[n:2n] (the a_dot slot) as ph
    g_cpg[i]         = yna * __cosf(ynad);
    g_cpg[N_OSC + i] = yna * __sinf(ynad);
}

// -------- launch helper with PDL attribute --------
template <typename K, typename... Args>
static void launch_pdl(K kernel, dim3 grid, dim3 block, Args... args) {
    cudaLaunchConfig_t cfg = {};
    cfg.gridDim = grid;
    cfg.blockDim = block;
    cudaLaunchAttribute attr[1];
    attr[0].id = cudaLaunchAttributeProgrammaticStreamSerialization;
    attr[0].val.programmaticStreamSerializationAllowed = 1;
    cfg.attrs = attr;
    cfg.numAttrs = 1;
    cudaLaunchKernelEx(&cfg, kernel, args...);
}

extern "C" void kernel_launch(void* const* d_in, const int* in_sizes, int n_in,
                              void* d_out, int out_size) {
    const float* state = (const float*)d_in[0];
    const float* x     = (const float*)d_in[1];
    const float* ts    = (const float*)d_in[2];
    const float* iW0   = (const float*)d_in[3];
    const float* ib0   = (const float*)d_in[4];
    const float* iW1   = (const float*)d_in[5];
    const float* ib1   = (const float*)d_in[6];
    const float* iW2   = (const float*)d_in[7];
    const float* ib2   = (const float*)d_in[8];
    const float* oW0   = (const float*)d_in[9];
    const float* ob0   = (const float*)d_in[10];
    const float* oW1   = (const float*)d_in[11];
    const float* ob1   = (const float*)d_in[12];
    const float* oW2   = (const float*)d_in[13];
    const float* ob2   = (const float*)d_in[14];
    float* out = (float*)d_out;   // [new_state(96), out(1024)]

    float* h1;  cudaGetSymbolAddress((void**)&h1,  g_h1);
    float* h2;  cudaGetSymbolAddress((void**)&h2,  g_h2);
    float* pr;  cudaGetSymbolAddress((void**)&pr,  g_params);
    float* cpg; cudaGetSymbolAddress((void**)&cpg, g_cpg);
    float* h3;  cudaGetSymbolAddress((void**)&h3,  g_h3);
    float* h4;  cudaGetSymbolAddress((void**)&h4,  g_h4);

    // L2-residency plan (L2 ~126 MB): iW0(33.6) + iW2(34.6) + oW1(16.8) +
    // oW2(8.4) + oW0(0.5) = ~94 MB resident (default .ca loads);
    // iW1 (67 MB) streamed with __ldcs so it never evicts the resident set.

    // 1) h1 = relu(iW0 @ [x, ts] + ib0)   [4096 x 2049]
    matvec_l1<<<4096, 256>>>(iW0, ib0, x, ts, h1);

    // 2) h2 = relu(iW1 @ h1 + ib1)        [4096 x 4096]  (STREAMED)
    launch_pdl(matvec_b<true, 1024, true>, dim3(4096), dim3(256), iW1, ib1, h1, h2);

    // 3) params = iW2 @ h2 + ib2          [2112 x 4096]
    launch_pdl(matvec_b<false, 1024, false>, dim3(2112), dim3(256), iW2, ib2, h2, pr);

    // 4) RK4 step + cpg_out; writes new_state to d_out[0:96]
    launch_pdl(cpg_ode_kernel, dim3(1), dim3(32), state, ts, out);

    // 5) h3 = relu(oW0 @ cpg + ob0)       [2048 x 64]
    launch_pdl(matvec_small64, dim3((2048 * 32) / 256), dim3(256), oW0, ob0, cpg, h3, 2048);

    // 6) h4 = relu(oW1 @ h3 + ob1)        [2048 x 2048]
    launch_pdl(matvec_b<true, 512, false>, dim3(2048), dim3(256), oW1, ob1, h3, h4);

    // 7) out = oW2 @ h4 + ob2             [1024 x 2048] -> d_out[96:1120]
    launch_pdl(matvec_b<false, 512, false>, dim3(1024), dim3(256), oW2, ob2, h4, out + 96);
}